// round 2
// baseline (speedup 1.0000x reference)
#include <cuda_runtime.h>
#include <math.h>

#define NP    16384
#define DIM   24
#define NPK   (DIM/2)     // 12 packed f32x2 per point
#define ESIG  65536
#define ERND  32768
#define KK    50          // reference keeps K+1 (self + K nearest)
#define CANDMAX 64        // per-row candidate capacity (>= KK+1)

#define SCAN_T  128       // threads per scan block
#define RPT     2         // rows per thread
#define ROWS_PB (SCAN_T*RPT)   // 256 rows per block
#define NROWB   (NP/ROWS_PB)   // 64
#define NCOLCH  16             // column chunks (grid.y)
#define CHCOLS  (NP/NCOLCH)    // 1024 columns per chunk
#define TCOL    128            // columns staged per shared tile

// ---------------- device state (no allocations allowed) ----------------
__device__ double g_acc[3];                 // [0]=signal, [1]=knn, [2]=rand
__device__ int    g_is64_sig, g_is64_rnd, g_is64_pid;
__device__ float  g_sq[NP];
__device__ int    g_pid[NP];
__device__ int    g_ccnt[NP];
__device__ float  g_cd2[NP][CANDMAX];
__device__ int    g_cidx[NP][CANDMAX];

// ---------------- helpers ----------------
__device__ __forceinline__ long long ldidx(const void* p, long long i, int is64) {
    if (is64) return ((const long long*)p)[i];
    return (long long)((const int*)p)[i];
}

__device__ __forceinline__ int detect64(const void* p, long long lim) {
    // int32 data read as int64 packs two values; high word is a random
    // in-range value -> out of [0,lim) with overwhelming probability.
    const long long* q = (const long long*)p;
    for (int i = 0; i < 32; i++) {
        long long v = q[i];
        if (v < 0 || v >= lim) return 0;
    }
    return 1;
}

__device__ __forceinline__ void fma2(unsigned long long& acc,
                                     unsigned long long a,
                                     unsigned long long b) {
    asm("fma.rn.f32x2 %0, %1, %2, %0;" : "+l"(acc) : "l"(a), "l"(b));
}

__device__ __forceinline__ float unpack_sum(unsigned long long v) {
    unsigned int lo, hi;
    asm("mov.b64 {%0, %1}, %2;" : "=r"(lo), "=r"(hi) : "l"(v));
    return __uint_as_float(lo) + __uint_as_float(hi);
}

template <int BS>
__device__ __forceinline__ void block_accum(double v, double* target) {
    __shared__ double s[BS];
    int t = threadIdx.x;
    s[t] = v;
    __syncthreads();
    for (int o = BS / 2; o > 0; o >>= 1) {
        if (t < o) s[t] += s[t + o];
        __syncthreads();
    }
    if (t == 0 && s[0] != 0.0) atomicAdd(target, s[0]);
}

// ---------------- small kernels ----------------
__global__ void k_init(const void* sig, const void* rnd, const void* pid) {
    if (threadIdx.x == 0 && blockIdx.x == 0) {
        g_acc[0] = 0.0; g_acc[1] = 0.0; g_acc[2] = 0.0;
        g_is64_sig = detect64(sig, (long long)NP);
        g_is64_rnd = detect64(rnd, (long long)NP);
        g_is64_pid = detect64(pid, 1LL << 31);
    }
}

__global__ void k_prep(const float* __restrict__ emb, const void* __restrict__ pid) {
    int i = blockIdx.x * blockDim.x + threadIdx.x;
    if (i < NP) {
        float s = 0.f;
        #pragma unroll
        for (int k = 0; k < DIM; k++) {
            float v = emb[i * DIM + k];
            s = fmaf(v, v, s);
        }
        g_sq[i]   = s;
        g_pid[i]  = (int)ldidx(pid, i, g_is64_pid);
        g_ccnt[i] = 0;
    }
}

__global__ void k_signal(const float* __restrict__ emb, const void* __restrict__ edges) {
    int i = blockIdx.x * blockDim.x + threadIdx.x;
    double v = 0.0;
    if (i < ESIG) {
        int is64 = g_is64_sig;
        long long a = ldidx(edges, i, is64);
        long long b = ldidx(edges, (long long)ESIG + i, is64);
        const float* pa = emb + a * DIM;
        const float* pb = emb + b * DIM;
        float s = 0.f;
        #pragma unroll
        for (int k = 0; k < DIM; k++) {
            float d = pa[k] - pb[k];
            s = fmaf(d, d, s);
        }
        v = (double)(s + 1e-12f);
    }
    block_accum<256>(v, &g_acc[0]);
}

__global__ void k_random(const float* __restrict__ emb, const void* __restrict__ edges) {
    int i = blockIdx.x * blockDim.x + threadIdx.x;
    double v = 0.0;
    if (i < ERND) {
        int is64 = g_is64_rnd;
        long long a = ldidx(edges, i, is64);
        long long b = ldidx(edges, (long long)ERND + i, is64);
        if (g_pid[a] != g_pid[b]) {
            const float* pa = emb + a * DIM;
            const float* pb = emb + b * DIM;
            float s = 0.f;
            #pragma unroll
            for (int k = 0; k < DIM; k++) {
                float d = pa[k] - pb[k];
                s = fmaf(d, d, s);
            }
            float dd = sqrtf(s + 1e-12f);
            if (dd < 1.0f) {
                float h = 1.0f - dd;
                v = (double)(h * h);
            }
        }
    }
    block_accum<256>(v, &g_acc[2]);
}

// ---------------- knn candidate scan ----------------
// grid (NROWB, NCOLCH). Each thread owns RPT rows; column tiles staged in
// shared memory. Dot products computed with packed fma.rn.f32x2 along D
// (halves = adjacent dims; dot = lo+hi at the end). Candidates (d2 < 1,
// including self) are pushed to per-row global lists (rare).
__global__ void __launch_bounds__(SCAN_T) k_scan(const float* __restrict__ emb) {
    __shared__ float4 scol[TCOL][DIM / 4];   // 12 KB
    __shared__ float  ssq[TCOL];

    int t = threadIdx.x;
    int r0 = blockIdx.x * ROWS_PB + t;
    int r1 = r0 + SCAN_T;
    int c0 = blockIdx.y * CHCOLS;

    // row registers as packed f32x2 (adjacent dims per 64-bit value)
    unsigned long long ra[NPK], rb[NPK];
    {
        const unsigned long long* g0 = (const unsigned long long*)(emb + (long long)r0 * DIM);
        const unsigned long long* g1 = (const unsigned long long*)(emb + (long long)r1 * DIM);
        #pragma unroll
        for (int q = 0; q < NPK; q++) { ra[q] = g0[q]; rb[q] = g1[q]; }
    }
    float sq0 = g_sq[r0], sq1 = g_sq[r1];

    for (int t0 = c0; t0 < c0 + CHCOLS; t0 += TCOL) {
        __syncthreads();
        {
            int c = t;  // SCAN_T == TCOL
            const float4* g4 = (const float4*)(emb + (long long)(t0 + c) * DIM);
            #pragma unroll
            for (int q = 0; q < DIM / 4; q++) scol[c][q] = g4[q];
            ssq[c] = g_sq[t0 + c];
        }
        __syncthreads();

        #pragma unroll 2
        for (int jj = 0; jj < TCOL; jj++) {
            const unsigned long long* cp = (const unsigned long long*)&scol[jj][0];
            unsigned long long a0 = 0ULL, a1 = 0ULL, b0 = 0ULL, b1 = 0ULL;
            #pragma unroll
            for (int q = 0; q < NPK; q += 2) {
                unsigned long long c_lo = cp[q], c_hi = cp[q + 1];
                fma2(a0, ra[q],     c_lo);
                fma2(a1, ra[q + 1], c_hi);
                fma2(b0, rb[q],     c_lo);
                fma2(b1, rb[q + 1], c_hi);
            }
            float sj  = ssq[jj];
            float dot0 = unpack_sum(a0) + unpack_sum(a1);
            float dot1 = unpack_sum(b0) + unpack_sum(b1);
            float d20 = sq0 + sj - 2.0f * dot0;
            float d21 = sq1 + sj - 2.0f * dot1;
            if (d20 < 1.0f) {
                int pos = atomicAdd(&g_ccnt[r0], 1);
                if (pos < CANDMAX) { g_cd2[r0][pos] = d20; g_cidx[r0][pos] = t0 + jj; }
            }
            if (d21 < 1.0f) {
                int pos = atomicAdd(&g_ccnt[r1], 1);
                if (pos < CANDMAX) { g_cd2[r1][pos] = d21; g_cidx[r1][pos] = t0 + jj; }
            }
        }
    }
}

// ---------------- finalize: per-row sort + hinge ----------------
__global__ void k_finalize(void) {
    int row = blockIdx.x * blockDim.x + threadIdx.x;
    double local = 0.0;
    if (row < NP) {
        int nc = g_ccnt[row];
        if (nc > CANDMAX) nc = CANDMAX;
        float cd2[CANDMAX];
        int   cidx[CANDMAX];
        for (int q = 0; q < nc; q++) { cd2[q] = g_cd2[row][q]; cidx[q] = g_cidx[row][q]; }
        // ascending by (d2, idx) -- matches stable top_k tie-break
        for (int i = 1; i < nc; i++) {
            float dv = cd2[i]; int iv = cidx[i];
            int j = i - 1;
            while (j >= 0 && (cd2[j] > dv || (cd2[j] == dv && cidx[j] > iv))) {
                cd2[j + 1] = cd2[j]; cidx[j + 1] = cidx[j]; j--;
            }
            cd2[j + 1] = dv; cidx[j + 1] = iv;
        }
        int mypid = g_pid[row];
        int lim = nc < (KK + 1) ? nc : (KK + 1);
        for (int q = 0; q < lim; q++) {
            int j = cidx[q];
            if (j != row && g_pid[j] != mypid) {
                float d = sqrtf(fmaxf(cd2[q], 0.0f) + 1e-12f);
                if (d < 1.0f) {
                    float h = 1.0f - d;
                    local += (double)(h * h);
                }
            }
        }
    }
    block_accum<256>(local, &g_acc[1]);
}

__global__ void k_finish(float* out) {
    if (threadIdx.x == 0 && blockIdx.x == 0) {
        out[0] = (float)(g_acc[0] / (double)ESIG +
                         g_acc[1] / (double)NP +
                         g_acc[2] / (double)ERND);
    }
}

// ---------------- launch ----------------
extern "C" void kernel_launch(void* const* d_in, const int* in_sizes, int n_in,
                              void* d_out, int out_size) {
    const float* emb = (const float*)d_in[0];
    const void*  sig = d_in[1];
    const void*  rnd = d_in[2];
    const void*  pid = d_in[3];
    float* out = (float*)d_out;

    k_init<<<1, 32>>>(sig, rnd, pid);
    k_prep<<<(NP + 255) / 256, 256>>>(emb, pid);
    k_signal<<<(ESIG + 255) / 256, 256>>>(emb, sig);
    k_random<<<(ERND + 255) / 256, 256>>>(emb, rnd);
    k_scan<<<dim3(NROWB, NCOLCH), SCAN_T>>>(emb);
    k_finalize<<<(NP + 255) / 256, 256>>>();
    k_finish<<<1, 32>>>(out);
}

// round 4
// speedup vs baseline: 2.9435x; 2.9435x over previous
#include <cuda_runtime.h>
#include <cuda_bf16.h>
#include <math.h>
#include <stdint.h>

#define NP    16384
#define DIM   24
#define KPAD  32          // bf16 row padded to 32 dims (64 B)
#define ESIG  65536
#define ERND  32768
#define KK    50          // reference keeps K+1 (self + K nearest)
#define CANDMAX 64
#define D2_SLACK 8.0f     // bf16 threshold (true cutoff 1.0; error bound ~1.2)

#define MT    128         // rows per CTA (8 warps x 16)
#define NT    128         // cols per staged tile
#define JG    8           // grid.y col groups
#define JT_PER ((NP/NT)/JG)   // 16 col tiles per CTA
#define AROW_W 20         // smem row stride in words (80 B) -> conflict-free frags

// ---------------- device state ----------------
__device__ double g_acc[3];                 // [0]=signal, [1]=knn, [2]=rand
__device__ int    g_is64_sig, g_is64_rnd, g_is64_pid;
__device__ float  g_sq[NP];
__device__ int    g_pid[NP];
__device__ int    g_ccnt[NP];
__device__ int    g_cidx[NP][CANDMAX];
__device__ __nv_bfloat16 g_bf[NP][KPAD];    // bf16 embeddings, zero-padded

// ---------------- helpers ----------------
__device__ __forceinline__ long long ldidx(const void* p, long long i, int is64) {
    if (is64) return ((const long long*)p)[i];
    return (long long)((const int*)p)[i];
}
__device__ __forceinline__ int detect64(const void* p, long long lim) {
    const long long* q = (const long long*)p;
    for (int i = 0; i < 32; i++) {
        long long v = q[i];
        if (v < 0 || v >= lim) return 0;
    }
    return 1;
}
template <int BS>
__device__ __forceinline__ void block_accum(double v, double* target) {
    __shared__ double s[BS];
    int t = threadIdx.x;
    s[t] = v;
    __syncthreads();
    for (int o = BS / 2; o > 0; o >>= 1) {
        if (t < o) s[t] += s[t + o];
        __syncthreads();
    }
    if (t == 0 && s[0] != 0.0) atomicAdd(target, s[0]);
}

// bf16 m16n8k16 mma: D = A*B + C (fp32 accum)
__device__ __forceinline__ void mma16816(float* d, const uint32_t* a, const uint32_t* b) {
    asm volatile(
        "mma.sync.aligned.m16n8k16.row.col.f32.bf16.bf16.f32 "
        "{%0,%1,%2,%3}, {%4,%5,%6,%7}, {%8,%9}, {%0,%1,%2,%3};"
        : "+f"(d[0]), "+f"(d[1]), "+f"(d[2]), "+f"(d[3])
        : "r"(a[0]), "r"(a[1]), "r"(a[2]), "r"(a[3]), "r"(b[0]), "r"(b[1]));
}

// ---------------- small kernels ----------------
__global__ void k_init(const void* sig, const void* rnd, const void* pid) {
    if (threadIdx.x == 0 && blockIdx.x == 0) {
        g_acc[0] = 0.0; g_acc[1] = 0.0; g_acc[2] = 0.0;
        g_is64_sig = detect64(sig, (long long)NP);
        g_is64_rnd = detect64(rnd, (long long)NP);
        g_is64_pid = detect64(pid, 1LL << 31);
    }
}

__global__ void k_prep(const float* __restrict__ emb, const void* __restrict__ pid) {
    int i = blockIdx.x * blockDim.x + threadIdx.x;
    if (i < NP) {
        float s = 0.f;
        #pragma unroll
        for (int k = 0; k < DIM; k++) {
            float v = emb[i * DIM + k];
            s = fmaf(v, v, s);
        }
        g_sq[i]   = s;
        g_pid[i]  = (int)ldidx(pid, i, g_is64_pid);
        g_ccnt[i] = 0;
        __nv_bfloat16* row = g_bf[i];
        #pragma unroll
        for (int k = 0; k < DIM; k++) row[k] = __float2bfloat16(emb[i * DIM + k]);
        #pragma unroll
        for (int k = DIM; k < KPAD; k++) row[k] = __float2bfloat16(0.f);
    }
}

__global__ void k_signal(const float* __restrict__ emb, const void* __restrict__ edges) {
    int i = blockIdx.x * blockDim.x + threadIdx.x;
    double v = 0.0;
    if (i < ESIG) {
        int is64 = g_is64_sig;
        long long a = ldidx(edges, i, is64);
        long long b = ldidx(edges, (long long)ESIG + i, is64);
        const float4* pa = (const float4*)(emb + a * DIM);  // 96B rows: 16B aligned
        const float4* pb = (const float4*)(emb + b * DIM);
        float s = 0.f;
        #pragma unroll
        for (int q = 0; q < DIM / 4; q++) {
            float4 x = pa[q], y = pb[q];
            float d0 = x.x - y.x, d1 = x.y - y.y, d2 = x.z - y.z, d3 = x.w - y.w;
            s = fmaf(d0, d0, s); s = fmaf(d1, d1, s);
            s = fmaf(d2, d2, s); s = fmaf(d3, d3, s);
        }
        v = (double)(s + 1e-12f);
    }
    block_accum<256>(v, &g_acc[0]);
}

__global__ void k_random(const float* __restrict__ emb, const void* __restrict__ edges) {
    int i = blockIdx.x * blockDim.x + threadIdx.x;
    double v = 0.0;
    if (i < ERND) {
        int is64 = g_is64_rnd;
        long long a = ldidx(edges, i, is64);
        long long b = ldidx(edges, (long long)ERND + i, is64);
        if (g_pid[a] != g_pid[b]) {
            const float4* pa = (const float4*)(emb + a * DIM);
            const float4* pb = (const float4*)(emb + b * DIM);
            float s = 0.f;
            #pragma unroll
            for (int q = 0; q < DIM / 4; q++) {
                float4 x = pa[q], y = pb[q];
                float d0 = x.x - y.x, d1 = x.y - y.y, d2 = x.z - y.z, d3 = x.w - y.w;
                s = fmaf(d0, d0, s); s = fmaf(d1, d1, s);
                s = fmaf(d2, d2, s); s = fmaf(d3, d3, s);
            }
            float dd = sqrtf(s + 1e-12f);
            if (dd < 1.0f) {
                float h = 1.0f - dd;
                v = (double)(h * h);
            }
        }
    }
    block_accum<256>(v, &g_acc[2]);
}

// ---------------- mma.sync candidate scan ----------------
// grid (NP/MT, JG), 256 threads (8 warps). Warp w owns rows [blk*128+w*16, +16).
// A/B staged in smem with 80B row stride: fragment lane->word map g*20+tig
// hits all 32 banks once (conflict-free). Per col tile: 16 n-blocks of
// m16n8k16 x 2 k-steps. d2_bf16 < 8 pushes candidate (incl. self); exact
// recheck in k_finalize.
__global__ void __launch_bounds__(256) k_scan_mma(void) {
    __shared__ uint32_t sA[MT * AROW_W];   // 10 KB
    __shared__ uint32_t sB[NT * AROW_W];   // 10 KB
    __shared__ float    sbsq[NT];

    int t    = threadIdx.x;
    int wid  = t >> 5;
    int lane = t & 31;
    int g    = lane >> 2;     // group
    int tig  = lane & 3;      // thread-in-group

    // stage A rows (128 rows x 64B real data, 4x16B chunks per row)
    {
        #pragma unroll
        for (int c = t; c < MT * 4; c += 256) {
            int row = c >> 2, i = c & 3;
            const uint4* src = (const uint4*)g_bf[blockIdx.x * MT + row];
            *(uint4*)&sA[row * AROW_W + i * 4] = src[i];
        }
    }
    __syncthreads();

    // A fragments for this warp's 16-row strip (2 k-steps x 4 regs), loaded once
    int sbase = wid * 16;                 // strip base row within tile
    uint32_t afr[2][4];
    {
        int r0 = (sbase + g) * AROW_W;
        int r1 = (sbase + g + 8) * AROW_W;
        afr[0][0] = sA[r0 + tig];       afr[0][1] = sA[r1 + tig];
        afr[0][2] = sA[r0 + tig + 4];   afr[0][3] = sA[r1 + tig + 4];
        afr[1][0] = sA[r0 + tig + 8];   afr[1][1] = sA[r1 + tig + 8];
        afr[1][2] = sA[r0 + tig + 12];  afr[1][3] = sA[r1 + tig + 12];
    }
    int rowg0 = blockIdx.x * MT + sbase + g;       // global row for d0,d1
    int rowg1 = rowg0 + 8;                          // global row for d2,d3
    float sq0 = g_sq[rowg0], sq1 = g_sq[rowg1];

    for (int jt = 0; jt < JT_PER; jt++) {
        int cbase = (blockIdx.y * JT_PER + jt) * NT;
        __syncthreads();
        {
            #pragma unroll
            for (int c = t; c < NT * 4; c += 256) {
                int col = c >> 2, i = c & 3;
                const uint4* src = (const uint4*)g_bf[cbase + col];
                *(uint4*)&sB[col * AROW_W + i * 4] = src[i];
            }
            if (t < NT) sbsq[t] = g_sq[cbase + t];
        }
        __syncthreads();

        #pragma unroll 4
        for (int nb = 0; nb < NT / 8; nb++) {
            int cb = nb * 8;
            int bq = (cb + g) * AROW_W;
            uint32_t bfr0[2], bfr1[2];
            bfr0[0] = sB[bq + tig];      bfr0[1] = sB[bq + tig + 4];   // k-step 0
            bfr1[0] = sB[bq + tig + 8];  bfr1[1] = sB[bq + tig + 12];  // k-step 1

            float d[4] = {0.f, 0.f, 0.f, 0.f};
            mma16816(d, afr[0], bfr0);
            mma16816(d, afr[1], bfr1);

            int c0 = cb + tig * 2;
            float sb0 = sbsq[c0], sb1 = sbsq[c0 + 1];
            float d200 = fmaf(-2.0f, d[0], sq0 + sb0);
            float d201 = fmaf(-2.0f, d[1], sq0 + sb1);
            float d210 = fmaf(-2.0f, d[2], sq1 + sb0);
            float d211 = fmaf(-2.0f, d[3], sq1 + sb1);
            if (d200 < D2_SLACK) {
                int p = atomicAdd(&g_ccnt[rowg0], 1);
                if (p < CANDMAX) g_cidx[rowg0][p] = cbase + c0;
            }
            if (d201 < D2_SLACK) {
                int p = atomicAdd(&g_ccnt[rowg0], 1);
                if (p < CANDMAX) g_cidx[rowg0][p] = cbase + c0 + 1;
            }
            if (d210 < D2_SLACK) {
                int p = atomicAdd(&g_ccnt[rowg1], 1);
                if (p < CANDMAX) g_cidx[rowg1][p] = cbase + c0;
            }
            if (d211 < D2_SLACK) {
                int p = atomicAdd(&g_ccnt[rowg1], 1);
                if (p < CANDMAX) g_cidx[rowg1][p] = cbase + c0 + 1;
            }
        }
    }
}

// ---------------- finalize: exact recompute + sort + hinge ----------------
__global__ void k_finalize(const float* __restrict__ emb) {
    int row = blockIdx.x * blockDim.x + threadIdx.x;
    double local = 0.0;
    if (row < NP) {
        int nc = g_ccnt[row];
        if (nc > CANDMAX) nc = CANDMAX;
        float cd2[CANDMAX];
        int   cidx[CANDMAX];
        float sqr = g_sq[row];
        const float4* pr = (const float4*)(emb + (long long)row * DIM);
        float4 r4[DIM / 4];
        #pragma unroll
        for (int q = 0; q < DIM / 4; q++) r4[q] = pr[q];
        for (int qq = 0; qq < nc; qq++) {
            int j = g_cidx[row][qq];
            const float4* pc = (const float4*)(emb + (long long)j * DIM);
            float dot = 0.f;
            #pragma unroll
            for (int q = 0; q < DIM / 4; q++) {
                float4 y = pc[q];
                dot = fmaf(r4[q].x, y.x, dot); dot = fmaf(r4[q].y, y.y, dot);
                dot = fmaf(r4[q].z, y.z, dot); dot = fmaf(r4[q].w, y.w, dot);
            }
            cd2[qq]  = sqr + g_sq[j] - 2.0f * dot;   // exact fp32, reference formula
            cidx[qq] = j;
        }
        for (int i = 1; i < nc; i++) {               // ascending (d2, idx)
            float dv = cd2[i]; int iv = cidx[i];
            int j = i - 1;
            while (j >= 0 && (cd2[j] > dv || (cd2[j] == dv && cidx[j] > iv))) {
                cd2[j + 1] = cd2[j]; cidx[j + 1] = cidx[j]; j--;
            }
            cd2[j + 1] = dv; cidx[j + 1] = iv;
        }
        int mypid = g_pid[row];
        int lim = nc < (KK + 1) ? nc : (KK + 1);
        for (int q = 0; q < lim; q++) {
            int j = cidx[q];
            if (j != row && g_pid[j] != mypid) {
                float d = sqrtf(fmaxf(cd2[q], 0.0f) + 1e-12f);
                if (d < 1.0f) {
                    float h = 1.0f - d;
                    local += (double)(h * h);
                }
            }
        }
    }
    block_accum<256>(local, &g_acc[1]);
}

__global__ void k_finish(float* out) {
    if (threadIdx.x == 0 && blockIdx.x == 0) {
        out[0] = (float)(g_acc[0] / (double)ESIG +
                         g_acc[1] / (double)NP +
                         g_acc[2] / (double)ERND);
    }
}

// ---------------- launch ----------------
extern "C" void kernel_launch(void* const* d_in, const int* in_sizes, int n_in,
                              void* d_out, int out_size) {
    const float* emb = (const float*)d_in[0];
    const void*  sig = d_in[1];
    const void*  rnd = d_in[2];
    const void*  pid = d_in[3];
    float* out = (float*)d_out;

    k_init<<<1, 32>>>(sig, rnd, pid);
    k_prep<<<(NP + 255) / 256, 256>>>(emb, pid);
    k_signal<<<(ESIG + 255) / 256, 256>>>(emb, sig);
    k_random<<<(ERND + 255) / 256, 256>>>(emb, rnd);
    k_scan_mma<<<dim3(NP / MT, JG), 256>>>();
    k_finalize<<<(NP + 255) / 256, 256>>>(emb);
    k_finish<<<1, 32>>>(out);
}

// round 5
// speedup vs baseline: 3.4305x; 1.1655x over previous
#include <cuda_runtime.h>
#include <cuda_bf16.h>
#include <math.h>
#include <stdint.h>

#define NP    16384
#define DIM   24
#define KPAD  32          // bf16 row padded to 32 dims (64 B)
#define ESIG  65536
#define ERND  32768
#define KK    50          // reference keeps K+1 (self + K nearest)
#define CANDMAX 64
#define D2_SLACK 8.0f     // bf16 threshold (true cutoff 1.0; error bound ~1.2)

#define MT    128         // rows per CTA (8 warps x 16)
#define NT    128         // cols per staged tile
#define JG    8           // col groups
#define JT_PER ((NP/NT)/JG)   // 16 col tiles per CTA
#define AROW_W 20         // smem row stride in words (80 B) -> conflict-free frags

#define SCAN_BLKS  ((NP/MT)*JG)          // 1024
#define SIG_BLKS   (ESIG/(256*4))        // 64
#define RND_BLKS   (ERND/(256*4))        // 32
#define MEGA_BLKS  (SCAN_BLKS + SIG_BLKS + RND_BLKS)

// ---------------- device state ----------------
__device__ double g_acc[3];                 // [0]=signal, [1]=knn, [2]=rand
__device__ int    g_is64_sig, g_is64_rnd, g_is64_pid;
__device__ int    g_done;
__device__ float  g_sq[NP];
__device__ int    g_pid[NP];
__device__ int    g_ccnt[NP];
__device__ int    g_cidx[NP][CANDMAX];
__device__ __nv_bfloat16 g_bf[NP][KPAD];    // bf16 embeddings, zero-padded

// ---------------- helpers ----------------
__device__ __forceinline__ long long ldidx(const void* p, long long i, int is64) {
    if (is64) return ((const long long*)p)[i];
    return (long long)((const int*)p)[i];
}
__device__ __forceinline__ int detect64(const void* p, long long lim) {
    const long long* q = (const long long*)p;
    for (int i = 0; i < 32; i++) {
        long long v = q[i];
        if (v < 0 || v >= lim) return 0;
    }
    return 1;
}
template <int BS>
__device__ __forceinline__ void block_accum(double v, double* target) {
    __shared__ double s[BS];
    int t = threadIdx.x;
    s[t] = v;
    __syncthreads();
    for (int o = BS / 2; o > 0; o >>= 1) {
        if (t < o) s[t] += s[t + o];
        __syncthreads();
    }
    if (t == 0 && s[0] != 0.0) atomicAdd(target, s[0]);
}

// bf16 m16n8k16 mma: D = A*B + C (fp32 accum)
__device__ __forceinline__ void mma16816(float* d, const uint32_t* a, const uint32_t* b) {
    asm volatile(
        "mma.sync.aligned.m16n8k16.row.col.f32.bf16.bf16.f32 "
        "{%0,%1,%2,%3}, {%4,%5,%6,%7}, {%8,%9}, {%0,%1,%2,%3};"
        : "+f"(d[0]), "+f"(d[1]), "+f"(d[2]), "+f"(d[3])
        : "r"(a[0]), "r"(a[1]), "r"(a[2]), "r"(a[3]), "r"(b[0]), "r"(b[1]));
}

__device__ __forceinline__ float edge_d2(const float* __restrict__ emb,
                                         long long a, long long b) {
    const float4* pa = (const float4*)(emb + a * DIM);  // 96B rows: 16B aligned
    const float4* pb = (const float4*)(emb + b * DIM);
    float s = 0.f;
    #pragma unroll
    for (int q = 0; q < DIM / 4; q++) {
        float4 x = pa[q], y = pb[q];
        float d0 = x.x - y.x, d1 = x.y - y.y, d2 = x.z - y.z, d3 = x.w - y.w;
        s = fmaf(d0, d0, s); s = fmaf(d1, d1, s);
        s = fmaf(d2, d2, s); s = fmaf(d3, d3, s);
    }
    return s;
}

// ---------------- init + prep ----------------
__global__ void k_init(const void* sig, const void* rnd, const void* pid) {
    if (threadIdx.x == 0 && blockIdx.x == 0) {
        g_acc[0] = 0.0; g_acc[1] = 0.0; g_acc[2] = 0.0;
        g_done = 0;
        g_is64_sig = detect64(sig, (long long)NP);
        g_is64_rnd = detect64(rnd, (long long)NP);
        g_is64_pid = detect64(pid, 1LL << 31);
    }
}

__global__ void k_prep(const float* __restrict__ emb, const void* __restrict__ pid) {
    int i = blockIdx.x * blockDim.x + threadIdx.x;
    if (i < NP) {
        float s = 0.f;
        #pragma unroll
        for (int k = 0; k < DIM; k++) {
            float v = emb[i * DIM + k];
            s = fmaf(v, v, s);
        }
        g_sq[i]   = s;
        g_pid[i]  = (int)ldidx(pid, i, g_is64_pid);
        g_ccnt[i] = 0;
        __nv_bfloat16* row = g_bf[i];
        #pragma unroll
        for (int k = 0; k < DIM; k++) row[k] = __float2bfloat16(emb[i * DIM + k]);
        #pragma unroll
        for (int k = DIM; k < KPAD; k++) row[k] = __float2bfloat16(0.f);
    }
}

// ---------------- mega kernel: scan + signal + random ----------------
// blocks [0, SCAN_BLKS): mma candidate scan
// blocks [SCAN_BLKS, +SIG_BLKS): signal loss, 4 edges/thread
// blocks [SCAN_BLKS+SIG_BLKS, +RND_BLKS): random loss, 4 edges/thread
__global__ void __launch_bounds__(256) k_mega(const float* __restrict__ emb,
                                              const void* __restrict__ sig,
                                              const void* __restrict__ rnd) {
    int bx = blockIdx.x;
    int t  = threadIdx.x;

    if (bx >= SCAN_BLKS) {
        if (bx < SCAN_BLKS + SIG_BLKS) {
            // ---- signal ----
            int base = (bx - SCAN_BLKS) * 256 * 4 + t * 4;
            int is64 = g_is64_sig;
            float s = 0.f;
            #pragma unroll
            for (int e = 0; e < 4; e++) {
                long long a = ldidx(sig, base + e, is64);
                long long b = ldidx(sig, (long long)ESIG + base + e, is64);
                s += edge_d2(emb, a, b) + 1e-12f;
            }
            block_accum<256>((double)s, &g_acc[0]);
        } else {
            // ---- random ----
            int base = (bx - SCAN_BLKS - SIG_BLKS) * 256 * 4 + t * 4;
            int is64 = g_is64_rnd;
            float s = 0.f;
            #pragma unroll
            for (int e = 0; e < 4; e++) {
                long long a = ldidx(rnd, base + e, is64);
                long long b = ldidx(rnd, (long long)ERND + base + e, is64);
                if (g_pid[a] != g_pid[b]) {
                    float dd = sqrtf(edge_d2(emb, a, b) + 1e-12f);
                    if (dd < 1.0f) {
                        float h = 1.0f - dd;
                        s += h * h;
                    }
                }
            }
            block_accum<256>((double)s, &g_acc[2]);
        }
        return;
    }

    // ---- scan ----
    __shared__ uint32_t sA[MT * AROW_W];   // 10 KB
    __shared__ uint32_t sB[NT * AROW_W];   // 10 KB
    __shared__ float    sbh[NT];           // 0.5 * sq of staged cols

    int rowblk = bx & (NP / MT - 1);       // 128 row tiles
    int cgrp   = bx >> 7;                  // 8 col groups
    int wid  = t >> 5;
    int lane = t & 31;
    int g    = lane >> 2;
    int tig  = lane & 3;

    // stage A rows
    #pragma unroll
    for (int c = t; c < MT * 4; c += 256) {
        int row = c >> 2, i = c & 3;
        const uint4* src = (const uint4*)g_bf[rowblk * MT + row];
        *(uint4*)&sA[row * AROW_W + i * 4] = src[i];
    }
    __syncthreads();

    // A fragments for this warp's 16-row strip
    int sbase = wid * 16;
    uint32_t afr[2][4];
    {
        int r0 = (sbase + g) * AROW_W;
        int r1 = (sbase + g + 8) * AROW_W;
        afr[0][0] = sA[r0 + tig];       afr[0][1] = sA[r1 + tig];
        afr[0][2] = sA[r0 + tig + 4];   afr[0][3] = sA[r1 + tig + 4];
        afr[1][0] = sA[r0 + tig + 8];   afr[1][1] = sA[r1 + tig + 8];
        afr[1][2] = sA[r0 + tig + 12];  afr[1][3] = sA[r1 + tig + 12];
    }
    int rowg0 = rowblk * MT + sbase + g;       // rows for d0,d1
    int rowg1 = rowg0 + 8;                      // rows for d2,d3
    // dot > thr + 0.5*sq_col  <=>  d2 < D2_SLACK
    float thr0 = 0.5f * (g_sq[rowg0] - D2_SLACK);
    float thr1 = 0.5f * (g_sq[rowg1] - D2_SLACK);
    float thrmin = fminf(thr0, thr1);

    for (int jt = 0; jt < JT_PER; jt++) {
        int cbase = (cgrp * JT_PER + jt) * NT;
        __syncthreads();
        #pragma unroll
        for (int c = t; c < NT * 4; c += 256) {
            int col = c >> 2, i = c & 3;
            const uint4* src = (const uint4*)g_bf[cbase + col];
            *(uint4*)&sB[col * AROW_W + i * 4] = src[i];
        }
        if (t < NT) sbh[t] = 0.5f * g_sq[cbase + t];
        __syncthreads();

        #pragma unroll 4
        for (int nb = 0; nb < NT / 8; nb++) {
            int cb = nb * 8;
            int bq = (cb + g) * AROW_W;
            uint32_t bfr0[2], bfr1[2];
            bfr0[0] = sB[bq + tig];      bfr0[1] = sB[bq + tig + 4];
            bfr1[0] = sB[bq + tig + 8];  bfr1[1] = sB[bq + tig + 12];

            float d[4] = {0.f, 0.f, 0.f, 0.f};
            mma16816(d, afr[0], bfr0);
            mma16816(d, afr[1], bfr1);

            int c0 = cb + tig * 2;
            float2 sb2 = *(const float2*)&sbh[c0];
            float dmax = fmaxf(fmaxf(d[0], d[1]), fmaxf(d[2], d[3]));
            if (dmax > thrmin + fminf(sb2.x, sb2.y)) {       // rare
                if (d[0] > thr0 + sb2.x) {
                    int p = atomicAdd(&g_ccnt[rowg0], 1);
                    if (p < CANDMAX) g_cidx[rowg0][p] = cbase + c0;
                }
                if (d[1] > thr0 + sb2.y) {
                    int p = atomicAdd(&g_ccnt[rowg0], 1);
                    if (p < CANDMAX) g_cidx[rowg0][p] = cbase + c0 + 1;
                }
                if (d[2] > thr1 + sb2.x) {
                    int p = atomicAdd(&g_ccnt[rowg1], 1);
                    if (p < CANDMAX) g_cidx[rowg1][p] = cbase + c0;
                }
                if (d[3] > thr1 + sb2.y) {
                    int p = atomicAdd(&g_ccnt[rowg1], 1);
                    if (p < CANDMAX) g_cidx[rowg1][p] = cbase + c0 + 1;
                }
            }
        }
    }
}

// ---------------- finalize: exact recompute + sort + hinge + finish ----------------
__global__ void k_finalize(const float* __restrict__ emb, float* out) {
    int row = blockIdx.x * blockDim.x + threadIdx.x;
    double local = 0.0;
    if (row < NP) {
        int nc = g_ccnt[row];
        if (nc > CANDMAX) nc = CANDMAX;
        float cd2[CANDMAX];
        int   cidx[CANDMAX];
        float sqr = g_sq[row];
        const float4* pr = (const float4*)(emb + (long long)row * DIM);
        float4 r4[DIM / 4];
        #pragma unroll
        for (int q = 0; q < DIM / 4; q++) r4[q] = pr[q];
        for (int qq = 0; qq < nc; qq++) {
            int j = g_cidx[row][qq];
            const float4* pc = (const float4*)(emb + (long long)j * DIM);
            float dot = 0.f;
            #pragma unroll
            for (int q = 0; q < DIM / 4; q++) {
                float4 y = pc[q];
                dot = fmaf(r4[q].x, y.x, dot); dot = fmaf(r4[q].y, y.y, dot);
                dot = fmaf(r4[q].z, y.z, dot); dot = fmaf(r4[q].w, y.w, dot);
            }
            cd2[qq]  = sqr + g_sq[j] - 2.0f * dot;   // exact fp32, reference formula
            cidx[qq] = j;
        }
        for (int i = 1; i < nc; i++) {               // ascending (d2, idx)
            float dv = cd2[i]; int iv = cidx[i];
            int j = i - 1;
            while (j >= 0 && (cd2[j] > dv || (cd2[j] == dv && cidx[j] > iv))) {
                cd2[j + 1] = cd2[j]; cidx[j + 1] = cidx[j]; j--;
            }
            cd2[j + 1] = dv; cidx[j + 1] = iv;
        }
        int mypid = g_pid[row];
        int lim = nc < (KK + 1) ? nc : (KK + 1);
        for (int q = 0; q < lim; q++) {
            int j = cidx[q];
            if (j != row && g_pid[j] != mypid) {
                float d = sqrtf(fmaxf(cd2[q], 0.0f) + 1e-12f);
                if (d < 1.0f) {
                    float h = 1.0f - d;
                    local += (double)(h * h);
                }
            }
        }
    }
    block_accum<256>(local, &g_acc[1]);

    // last block writes the final scalar
    if (threadIdx.x == 0) {
        __threadfence();
        int done = atomicAdd(&g_done, 1);
        if (done == (int)gridDim.x - 1) {
            out[0] = (float)(g_acc[0] / (double)ESIG +
                             g_acc[1] / (double)NP +
                             g_acc[2] / (double)ERND);
        }
    }
}

// ---------------- launch ----------------
extern "C" void kernel_launch(void* const* d_in, const int* in_sizes, int n_in,
                              void* d_out, int out_size) {
    const float* emb = (const float*)d_in[0];
    const void*  sig = d_in[1];
    const void*  rnd = d_in[2];
    const void*  pid = d_in[3];
    float* out = (float*)d_out;

    k_init<<<1, 32>>>(sig, rnd, pid);
    k_prep<<<(NP + 255) / 256, 256>>>(emb, pid);
    k_mega<<<MEGA_BLKS, 256>>>(emb, sig, rnd);
    k_finalize<<<(NP + 255) / 256, 256>>>(emb, out);
}

// round 6
// speedup vs baseline: 3.6390x; 1.0608x over previous
#include <cuda_runtime.h>
#include <cuda_bf16.h>
#include <math.h>
#include <stdint.h>

#define NP    16384
#define DIM   24
#define ESIG  65536
#define ERND  32768
#define KK    50          // reference keeps K+1 (self + K nearest)
#define CANDMAX 64
#define D2_SLACK 8.0f     // bf16 threshold (true cutoff 1.0; error bound ~1.2)

#define MT    128         // rows per CTA (8 warps x 16)
#define NT    128         // cols per staged tile
#define JG    8           // col groups
#define JT_PER ((NP/NT)/JG)   // 16 col tiles per CTA
#define AROW_W 24         // smem row stride in words (96 B): LDS.64 frag loads conflict-free

#define SIG_BLKS   (ESIG/(256*4))        // 64
#define RND_BLKS   (ERND/(256*4))        // 32
#define EDGE_BLKS  (SIG_BLKS + RND_BLKS) // 96
#define SCAN_BLKS  ((NP/MT)*JG)          // 1024
#define MEGA_BLKS  (EDGE_BLKS + SCAN_BLKS)

// ---------------- device state ----------------
__device__ double g_acc[3];                 // [0]=signal, [1]=knn, [2]=rand
__device__ int    g_done;
__device__ float  g_sq[NP];
__device__ float  g_sqh[NP];                // 0.5 * sq
__device__ int    g_pid[NP];
__device__ int    g_ccnt[NP];
__device__ int    g_cidx[NP][CANDMAX];
__device__ uint32_t g_bfw[NP][16];          // bf16x2 words, PERMUTED: [w0,w4,w1,w5,w2,w6,w3,w7, w8,w12,w9,w13,w10,w14,w11,w15]

// ---------------- helpers ----------------
__device__ __forceinline__ long long ldidx(const void* p, long long i, int is64) {
    if (is64) return ((const long long*)p)[i];
    return (long long)((const int*)p)[i];
}
__device__ __forceinline__ int detect64(const void* p, long long lim) {
    const long long* q = (const long long*)p;
    for (int i = 0; i < 32; i++) {
        long long v = q[i];
        if (v < 0 || v >= lim) return 0;
    }
    return 1;
}
template <int BS>
__device__ __forceinline__ void block_accum(double v, double* target) {
    __shared__ double s[BS];
    int t = threadIdx.x;
    s[t] = v;
    __syncthreads();
    for (int o = BS / 2; o > 0; o >>= 1) {
        if (t < o) s[t] += s[t + o];
        __syncthreads();
    }
    if (t == 0 && s[0] != 0.0) atomicAdd(target, s[0]);
}
__device__ __forceinline__ uint32_t smem_u32(const void* p) {
    uint32_t a;
    asm("{ .reg .u64 t; cvta.to.shared.u64 t, %1; cvt.u32.u64 %0, t; }" : "=r"(a) : "l"(p));
    return a;
}
__device__ __forceinline__ void cpa16(uint32_t s, const void* g) {
    asm volatile("cp.async.cg.shared.global [%0], [%1], 16;" :: "r"(s), "l"(g));
}
#define CPA_COMMIT() asm volatile("cp.async.commit_group;" ::: "memory")
#define CPA_WAIT0()  asm volatile("cp.async.wait_group 0;" ::: "memory")

// bf16 m16n8k16 mma: D = A*B + C (fp32 accum)
__device__ __forceinline__ void mma16816(float* d, const uint32_t* a, const uint32_t* b) {
    asm volatile(
        "mma.sync.aligned.m16n8k16.row.col.f32.bf16.bf16.f32 "
        "{%0,%1,%2,%3}, {%4,%5,%6,%7}, {%8,%9}, {%0,%1,%2,%3};"
        : "+f"(d[0]), "+f"(d[1]), "+f"(d[2]), "+f"(d[3])
        : "r"(a[0]), "r"(a[1]), "r"(a[2]), "r"(a[3]), "r"(b[0]), "r"(b[1]));
}

__device__ __forceinline__ float edge_d2(const float* __restrict__ emb,
                                         long long a, long long b) {
    const float4* pa = (const float4*)(emb + a * DIM);  // 96B rows: 16B aligned
    const float4* pb = (const float4*)(emb + b * DIM);
    float s = 0.f;
    #pragma unroll
    for (int q = 0; q < DIM / 4; q++) {
        float4 x = pa[q], y = pb[q];
        float d0 = x.x - y.x, d1 = x.y - y.y, d2 = x.z - y.z, d3 = x.w - y.w;
        s = fmaf(d0, d0, s); s = fmaf(d1, d1, s);
        s = fmaf(d2, d2, s); s = fmaf(d3, d3, s);
    }
    return s;
}

// ---------------- prep (also zeroes accumulators) ----------------
__global__ void k_prep(const float* __restrict__ emb, const void* __restrict__ pid) {
    __shared__ int s_is64;
    if (threadIdx.x == 0) s_is64 = detect64(pid, 1LL << 31);
    if (blockIdx.x == 0 && threadIdx.x == 0) {
        g_acc[0] = 0.0; g_acc[1] = 0.0; g_acc[2] = 0.0;
        g_done = 0;
    }
    __syncthreads();
    int i = blockIdx.x * blockDim.x + threadIdx.x;
    if (i < NP) {
        float v[32];
        float s = 0.f;
        #pragma unroll
        for (int k = 0; k < DIM; k++) {
            v[k] = emb[i * DIM + k];
            s = fmaf(v[k], v[k], s);
        }
        #pragma unroll
        for (int k = DIM; k < 32; k++) v[k] = 0.f;
        g_sq[i]   = s;
        g_sqh[i]  = 0.5f * s;
        g_pid[i]  = (int)ldidx(pid, i, s_is64);
        g_ccnt[i] = 0;
        uint32_t w[16];
        #pragma unroll
        for (int j = 0; j < 16; j++) {
            __nv_bfloat162 p = __floats2bfloat162_rn(v[2 * j], v[2 * j + 1]);
            w[j] = *(uint32_t*)&p;
        }
        uint32_t* dst = g_bfw[i];
        #pragma unroll
        for (int j = 0; j < 4; j++) { dst[2 * j] = w[j]; dst[2 * j + 1] = w[j + 4]; }
        #pragma unroll
        for (int j = 0; j < 4; j++) { dst[8 + 2 * j] = w[8 + j]; dst[9 + 2 * j] = w[12 + j]; }
    }
}

// ---------------- mega kernel: edges first, then scan ----------------
__global__ void __launch_bounds__(256) k_mega(const float* __restrict__ emb,
                                              const void* __restrict__ sig,
                                              const void* __restrict__ rnd) {
    int bx = blockIdx.x;
    int t  = threadIdx.x;

    if (bx < EDGE_BLKS) {
        __shared__ int s_is64;
        if (bx < SIG_BLKS) {
            if (t == 0) s_is64 = detect64(sig, (long long)NP);
            __syncthreads();
            int base = bx * 256 * 4 + t * 4;
            int is64 = s_is64;
            float s = 0.f;
            #pragma unroll
            for (int e = 0; e < 4; e++) {
                long long a = ldidx(sig, base + e, is64);
                long long b = ldidx(sig, (long long)ESIG + base + e, is64);
                s += edge_d2(emb, a, b) + 1e-12f;
            }
            block_accum<256>((double)s, &g_acc[0]);
        } else {
            if (t == 0) s_is64 = detect64(rnd, (long long)NP);
            __syncthreads();
            int base = (bx - SIG_BLKS) * 256 * 4 + t * 4;
            int is64 = s_is64;
            float s = 0.f;
            #pragma unroll
            for (int e = 0; e < 4; e++) {
                long long a = ldidx(rnd, base + e, is64);
                long long b = ldidx(rnd, (long long)ERND + base + e, is64);
                if (g_pid[a] != g_pid[b]) {
                    float dd = sqrtf(edge_d2(emb, a, b) + 1e-12f);
                    if (dd < 1.0f) {
                        float h = 1.0f - dd;
                        s += h * h;
                    }
                }
            }
            block_accum<256>((double)s, &g_acc[2]);
        }
        return;
    }

    // ---- scan ----
    __shared__ uint32_t sA[MT * AROW_W];        // 12 KB
    __shared__ uint32_t sB[2][NT * AROW_W];     // 24 KB double-buffered
    __shared__ float    sbh[2][NT];             // 0.5*sq of staged cols

    int sbx    = bx - EDGE_BLKS;
    int rowblk = sbx & (NP / MT - 1);
    int cgrp   = sbx >> 7;
    int wid  = t >> 5;
    int lane = t & 31;
    int g    = lane >> 2;
    int tig  = lane & 3;

    // stage A (4 chunks/thread) + B tile 0 (2 chunks/thread) + sbh[0] via cp.async
    {
        #pragma unroll
        for (int c = t; c < MT * 4; c += 256) {
            int row = c >> 2, i = c & 3;
            cpa16(smem_u32(&sA[row * AROW_W + i * 4]), &g_bfw[rowblk * MT + row][i * 4]);
        }
        int cbase0 = cgrp * JT_PER * NT;
        #pragma unroll
        for (int c = t; c < NT * 4; c += 256) {
            int col = c >> 2, i = c & 3;
            cpa16(smem_u32(&sB[0][col * AROW_W + i * 4]), &g_bfw[cbase0 + col][i * 4]);
        }
        if (t < NT / 4) cpa16(smem_u32(&sbh[0][t * 4]), &g_sqh[cbase0 + t * 4]);
        CPA_COMMIT();
        CPA_WAIT0();
    }
    __syncthreads();

    // A fragments for this warp's 16-row strip (LDS.64 pairs, permuted layout)
    int sbase = wid * 16;
    uint32_t afr[2][4];
    {
        int r0 = (sbase + g) * AROW_W;
        int r1 = (sbase + g + 8) * AROW_W;
        uint2 p;
        p = *(const uint2*)&sA[r0 + 2 * tig];     afr[0][0] = p.x; afr[0][2] = p.y;
        p = *(const uint2*)&sA[r1 + 2 * tig];     afr[0][1] = p.x; afr[0][3] = p.y;
        p = *(const uint2*)&sA[r0 + 8 + 2 * tig]; afr[1][0] = p.x; afr[1][2] = p.y;
        p = *(const uint2*)&sA[r1 + 8 + 2 * tig]; afr[1][1] = p.x; afr[1][3] = p.y;
    }
    int rowg0 = rowblk * MT + sbase + g;
    int rowg1 = rowg0 + 8;
    float thr0 = 0.5f * (g_sq[rowg0] - D2_SLACK);   // dot > thr + 0.5*sq_col <=> d2 < slack
    float thr1 = 0.5f * (g_sq[rowg1] - D2_SLACK);
    float thrmin = fminf(thr0, thr1);

    for (int jt = 0; jt < JT_PER; jt++) {
        int buf = jt & 1;
        int cbase = (cgrp * JT_PER + jt) * NT;

        if (jt + 1 < JT_PER) {       // prefetch next tile into other buffer
            int cb1 = cbase + NT;
            int nb  = buf ^ 1;
            #pragma unroll
            for (int c = t; c < NT * 4; c += 256) {
                int col = c >> 2, i = c & 3;
                cpa16(smem_u32(&sB[nb][col * AROW_W + i * 4]), &g_bfw[cb1 + col][i * 4]);
            }
            if (t < NT / 4) cpa16(smem_u32(&sbh[nb][t * 4]), &g_sqh[cb1 + t * 4]);
            CPA_COMMIT();
        }

        const uint32_t* B = sB[buf];
        const float*    SH = sbh[buf];
        #pragma unroll 4
        for (int nb = 0; nb < NT / 8; nb++) {
            int cb = nb * 8;
            int bq = (cb + g) * AROW_W + 2 * tig;
            uint2 b0 = *(const uint2*)&B[bq];        // k-step 0
            uint2 b1 = *(const uint2*)&B[bq + 8];    // k-step 1

            float d[4] = {0.f, 0.f, 0.f, 0.f};
            uint32_t bf0[2] = {b0.x, b0.y};
            uint32_t bf1[2] = {b1.x, b1.y};
            mma16816(d, afr[0], bf0);
            mma16816(d, afr[1], bf1);

            int c0 = cb + tig * 2;
            float2 sb2 = *(const float2*)&SH[c0];
            float dmax = fmaxf(fmaxf(d[0], d[1]), fmaxf(d[2], d[3]));
            if (dmax > thrmin + fminf(sb2.x, sb2.y)) {       // rare
                if (d[0] > thr0 + sb2.x) {
                    int p = atomicAdd(&g_ccnt[rowg0], 1);
                    if (p < CANDMAX) g_cidx[rowg0][p] = cbase + c0;
                }
                if (d[1] > thr0 + sb2.y) {
                    int p = atomicAdd(&g_ccnt[rowg0], 1);
                    if (p < CANDMAX) g_cidx[rowg0][p] = cbase + c0 + 1;
                }
                if (d[2] > thr1 + sb2.x) {
                    int p = atomicAdd(&g_ccnt[rowg1], 1);
                    if (p < CANDMAX) g_cidx[rowg1][p] = cbase + c0;
                }
                if (d[3] > thr1 + sb2.y) {
                    int p = atomicAdd(&g_ccnt[rowg1], 1);
                    if (p < CANDMAX) g_cidx[rowg1][p] = cbase + c0 + 1;
                }
            }
        }
        CPA_WAIT0();
        __syncthreads();   // next buffer arrived; all warps done with this one
    }
}

// ---------------- finalize: fast-path + exact recompute + hinge + finish ----------------
__global__ void k_finalize(const float* __restrict__ emb, float* out) {
    int row = blockIdx.x * blockDim.x + threadIdx.x;
    double local = 0.0;
    int nc = (row < NP) ? g_ccnt[row] : 0;
    if (nc > CANDMAX) nc = CANDMAX;
    if (nc > 1) {      // nc==1 => only self (always pushed) => contributes 0
        float cd2[CANDMAX];
        int   cidx[CANDMAX];
        float sqr = g_sq[row];
        const float4* pr = (const float4*)(emb + (long long)row * DIM);
        float4 r4[DIM / 4];
        #pragma unroll
        for (int q = 0; q < DIM / 4; q++) r4[q] = pr[q];
        for (int qq = 0; qq < nc; qq++) {
            int j = g_cidx[row][qq];
            const float4* pc = (const float4*)(emb + (long long)j * DIM);
            float dot = 0.f;
            #pragma unroll
            for (int q = 0; q < DIM / 4; q++) {
                float4 y = pc[q];
                dot = fmaf(r4[q].x, y.x, dot); dot = fmaf(r4[q].y, y.y, dot);
                dot = fmaf(r4[q].z, y.z, dot); dot = fmaf(r4[q].w, y.w, dot);
            }
            cd2[qq]  = sqr + g_sq[j] - 2.0f * dot;   // exact fp32, reference formula
            cidx[qq] = j;
        }
        for (int i = 1; i < nc; i++) {               // ascending (d2, idx)
            float dv = cd2[i]; int iv = cidx[i];
            int j = i - 1;
            while (j >= 0 && (cd2[j] > dv || (cd2[j] == dv && cidx[j] > iv))) {
                cd2[j + 1] = cd2[j]; cidx[j + 1] = cidx[j]; j--;
            }
            cd2[j + 1] = dv; cidx[j + 1] = iv;
        }
        int mypid = g_pid[row];
        int lim = nc < (KK + 1) ? nc : (KK + 1);
        for (int q = 0; q < lim; q++) {
            int j = cidx[q];
            if (j != row && g_pid[j] != mypid) {
                float d = sqrtf(fmaxf(cd2[q], 0.0f) + 1e-12f);
                if (d < 1.0f) {
                    float h = 1.0f - d;
                    local += (double)(h * h);
                }
            }
        }
    }
    block_accum<256>(local, &g_acc[1]);

    if (threadIdx.x == 0) {
        __threadfence();
        int done = atomicAdd(&g_done, 1);
        if (done == (int)gridDim.x - 1) {
            out[0] = (float)(g_acc[0] / (double)ESIG +
                             g_acc[1] / (double)NP +
                             g_acc[2] / (double)ERND);
        }
    }
}

// ---------------- launch ----------------
extern "C" void kernel_launch(void* const* d_in, const int* in_sizes, int n_in,
                              void* d_out, int out_size) {
    const float* emb = (const float*)d_in[0];
    const void*  sig = d_in[1];
    const void*  rnd = d_in[2];
    const void*  pid = d_in[3];
    float* out = (float*)d_out;

    k_prep<<<(NP + 255) / 256, 256>>>(emb, pid);
    k_mega<<<MEGA_BLKS, 256>>>(emb, sig, rnd);
    k_finalize<<<(NP + 255) / 256, 256>>>(emb, out);
}